// round 8
// baseline (speedup 1.0000x reference)
#include <cuda_runtime.h>
#include <cuda_bf16.h>
#include <cstdint>

#define NN 300000
#define EE 600000
#define HH 128
#define GG 8192

// ---------------- scratch (device globals: allocation-free) ----------------
__device__ float g_P[(size_t)NN * HH];    // prev-layer raw output (atom enc / y2 pre-BN)
__device__ float g_HIN[(size_t)NN * HH];  // h_in
__device__ float g_Y1[(size_t)NN * HH];   // y1 (pre-BN1 GEMM1 output)
__device__ float g_pool[(size_t)GG * HH];
__device__ float g_stats[4 * HH];         // [sum1, sumsq1, sum2, sumsq2]
__device__ float g_bn[4 * HH];            // slots 2,3 = mu2, rstd2 (BN2 only)
__device__ __nv_bfloat16 g_Wh[10 * HH * HH];
__device__ __nv_bfloat16 g_Wl[10 * HH * HH];
// CSR by row (payload cidx) for bond sums; CSC by col (payload row) for aggr gather
__device__ int g_cnt[NN],  g_cur[NN],  g_off[NN + 1];
__device__ int g_cnt2[NN], g_cur2[NN], g_off2[NN + 1];
__device__ unsigned int g_pack[EE];    // cidx (bond table index)
__device__ int g_pack2[EE];            // src row
// precombined bond tables: [5][216][128]
__device__ float g_ctab[5 * 216 * HH];

__device__ __forceinline__ void red_add_v4(float* p, float4 v) {
    asm volatile("red.global.add.v4.f32 [%0], {%1,%2,%3,%4};"
                 :: "l"(p), "f"(v.x), "f"(v.y), "f"(v.z), "f"(v.w) : "memory");
}
__device__ __forceinline__ uint32_t smem_u32(const void* p) {
    uint32_t a;
    asm("{ .reg .u64 t; cvta.to.shared.u64 t, %1; cvt.u32.u64 %0, t; }" : "=r"(a) : "l"(p));
    return a;
}
__device__ __forceinline__ void ldsm4(uint32_t* r, uint32_t addr) {
    asm volatile("ldmatrix.sync.aligned.m8n8.x4.shared.b16 {%0,%1,%2,%3}, [%4];"
                 : "=r"(r[0]), "=r"(r[1]), "=r"(r[2]), "=r"(r[3]) : "r"(addr));
}
__device__ __forceinline__ void mma16816(float* d, const uint32_t* a, const uint32_t* b) {
    asm volatile("mma.sync.aligned.m16n8k16.row.col.f32.bf16.bf16.f32 "
                 "{%0,%1,%2,%3}, {%4,%5,%6,%7}, {%8,%9}, {%0,%1,%2,%3};"
                 : "+f"(d[0]), "+f"(d[1]), "+f"(d[2]), "+f"(d[3])
                 : "r"(a[0]), "r"(a[1]), "r"(a[2]), "r"(a[3]), "r"(b[0]), "r"(b[1]));
}

// ---------------- setup kernels ----------------
__global__ void k_init() {
    size_t stride = (size_t)gridDim.x * blockDim.x;
    size_t i0 = (size_t)blockIdx.x * blockDim.x + threadIdx.x;
    for (size_t i = i0; i < (size_t)NN; i += stride) {
        g_cnt[i] = 0; g_cur[i] = 0; g_cnt2[i] = 0; g_cur2[i] = 0;
    }
    for (size_t i = i0; i < (size_t)GG * HH; i += stride) g_pool[i] = 0.f;
}

__global__ void k_prepw(const float* __restrict__ w1, const float* __restrict__ w2) {
    int l = blockIdx.y;   // 0..9
    const float* W = (l < 5) ? (w1 + (size_t)l * HH * HH) : (w2 + (size_t)(l - 5) * HH * HH);
    int slot = (l < 5) ? (2 * l) : (2 * (l - 5) + 1);
    int q = blockIdx.x * 256 + threadIdx.x;
    int k = q >> 5, n0 = (q & 31) * 4;
    float4 w = *(const float4*)(W + (size_t)k * HH + n0);
    float wv[4] = {w.x, w.y, w.z, w.w};
#pragma unroll
    for (int j = 0; j < 4; j++) {
        __nv_bfloat16 h = __float2bfloat16(wv[j]);
        size_t o = (size_t)slot * HH * HH + (size_t)(n0 + j) * HH + k;
        g_Wh[o] = h;
        g_Wl[o] = __float2bfloat16(wv[j] - __bfloat162float(h));
    }
}

__global__ void k_prepbond(const float* __restrict__ bemb) {
    int c = blockIdx.x;   // 0..215
    int l = blockIdx.y;   // 0..4
    int h = threadIdx.x;  // 0..127
    int a0 = c / 36, a1 = (c / 6) % 6, a2 = c % 6;
    const float* b = bemb + (size_t)l * 3 * 8 * HH;
    g_ctab[((size_t)l * 216 + c) * HH + h] =
        b[(size_t)(0 * 8 + a0) * HH + h] + b[(size_t)(1 * 8 + a1) * HH + h]
        + b[(size_t)(2 * 8 + a2) * HH + h];
}

__global__ void k_atom(const int* __restrict__ x, const float* __restrict__ aemb) {
    int idx = blockIdx.x * blockDim.x + threadIdx.x;
    int n = idx >> 5; if (n >= NN) return;
    int c = (idx & 31) << 2;
    float4 acc = make_float4(0.f, 0.f, 0.f, 0.f);
#pragma unroll
    for (int f = 0; f < 9; f++) {
        int xi = __ldg(x + n * 9 + f);
        float4 e = *(const float4*)(aemb + ((size_t)(f * 128 + xi) * HH + c));
        acc.x += e.x; acc.y += e.y; acc.z += e.z; acc.w += e.w;
    }
    *(float4*)(g_P + (size_t)n * HH + c) = acc;
}

__global__ void k_cnt(const int* __restrict__ row, const int* __restrict__ col) {
    int e = blockIdx.x * blockDim.x + threadIdx.x;
    if (e < EE) {
        atomicAdd(&g_cnt[__ldg(row + e)], 1);
        atomicAdd(&g_cnt2[__ldg(col + e)], 1);
    }
}

// exclusive scan: block 0 -> (cnt,off), block 1 -> (cnt2,off2)
__global__ void k_scan() {
    __shared__ int bs[1024];
    const int* cnt = (blockIdx.x == 0) ? g_cnt : g_cnt2;
    int* off = (blockIdx.x == 0) ? g_off : g_off2;
    const int t = threadIdx.x;
    const int C = (NN + 1023) / 1024;   // 293
    int base = t * C;
    int s = 0;
    for (int i = 0; i < C; i++) {
        int idx = base + i;
        if (idx < NN) s += cnt[idx];
    }
    bs[t] = s;
    __syncthreads();
    for (int o = 1; o < 1024; o <<= 1) {
        int u = (t >= o) ? bs[t - o] : 0;
        __syncthreads();
        bs[t] += u;
        __syncthreads();
    }
    int run = bs[t] - s;
    for (int i = 0; i < C; i++) {
        int idx = base + i;
        if (idx < NN) { off[idx] = run; run += cnt[idx]; }
    }
    if (t == 1023) off[NN] = EE;
}

__global__ void k_fill(const int* __restrict__ row, const int* __restrict__ col,
                       const int* __restrict__ eattr) {
    int e = blockIdx.x * blockDim.x + threadIdx.x;
    if (e >= EE) return;
    int r = __ldg(row + e);
    int c = __ldg(col + e);
    int a0 = __ldg(eattr + e * 3 + 0);
    int a1 = __ldg(eattr + e * 3 + 1);
    int a2 = __ldg(eattr + e * 3 + 2);
    int pos = g_off[r] + atomicAdd(&g_cur[r], 1);
    g_pack[pos] = (unsigned int)(a0 * 36 + a1 * 6 + a2);
    int pos2 = g_off2[c] + atomicAdd(&g_cur2[c], 1);
    g_pack2[pos2] = r;
}

// ---------------- node kernel (bond sum + BN2 + hin) ----------------
// warp per node; block 0 zeroes stats slot0 for upcoming GEMM1.
template<int FIRST>
__global__ void __launch_bounds__(256)
k_node(int layer, const float* __restrict__ bg, const float* __restrict__ bb) {
    __shared__ float s_sc[HH], s_sh[HH];
    const int tid = threadIdx.x;
    if (blockIdx.x == 0 && tid < 2 * HH) g_stats[tid] = 0.f;   // zero slot0
    if (!FIRST) {
        if (tid < HH) {
            float s = __ldg(bg + tid) * g_bn[3 * HH + tid];
            s_sc[tid] = s;
            s_sh[tid] = __ldg(bb + tid) - s * g_bn[2 * HH + tid];
        }
        __syncthreads();
    }
    const int n = blockIdx.x * 8 + (tid >> 5);
    if (n >= NN) return;
    const int c4 = (tid & 31) << 2;
    const float* ctab = g_ctab + (size_t)layer * 216 * HH;
    const int e0 = __ldg(&g_off[n]), e1 = __ldg(&g_off[n + 1]);
    const float inv = 1.f / ((float)(e1 - e0) + 1.f);

    // 2-way unrolled bond-table gather (dual accumulators for MLP)
    float4 bsum = make_float4(0.f, 0.f, 0.f, 0.f);
    float4 bsum2 = make_float4(0.f, 0.f, 0.f, 0.f);
    int e = e0;
    for (; e + 2 <= e1; e += 2) {
        unsigned int c0i = __ldg(&g_pack[e]);
        unsigned int c1i = __ldg(&g_pack[e + 1]);
        const float4 t0 = *(const float4*)(ctab + (size_t)c0i * HH + c4);
        const float4 t1 = *(const float4*)(ctab + (size_t)c1i * HH + c4);
        bsum.x += t0.x; bsum.y += t0.y; bsum.z += t0.z; bsum.w += t0.w;
        bsum2.x += t1.x; bsum2.y += t1.y; bsum2.z += t1.z; bsum2.w += t1.w;
    }
    if (e < e1) {
        unsigned int ci = __ldg(&g_pack[e]);
        const float4 t = *(const float4*)(ctab + (size_t)ci * HH + c4);
        bsum.x += t.x; bsum.y += t.y; bsum.z += t.z; bsum.w += t.w;
    }
    bsum.x += bsum2.x; bsum.y += bsum2.y; bsum.z += bsum2.z; bsum.w += bsum2.w;

    float4 p = *(const float4*)(g_P + (size_t)n * HH + c4);
    if (!FIRST) {
        p.x = fmaxf(fmaf(s_sc[c4 + 0], p.x, s_sh[c4 + 0]), 0.f);
        p.y = fmaxf(fmaf(s_sc[c4 + 1], p.y, s_sh[c4 + 1]), 0.f);
        p.z = fmaxf(fmaf(s_sc[c4 + 2], p.z, s_sh[c4 + 2]), 0.f);
        p.w = fmaxf(fmaf(s_sc[c4 + 3], p.w, s_sh[c4 + 3]), 0.f);
    }
    float4 h;
    h.x = fmaf(bsum.x, inv, p.x);
    h.y = fmaf(bsum.y, inv, p.y);
    h.z = fmaf(bsum.z, inv, p.z);
    h.w = fmaf(bsum.w, inv, p.w);
    *(float4*)(g_HIN + (size_t)n * HH + c4) = h;
}

// ---------------- HMMA bf16-split GEMM, M-tile 64, 2 CTAs/SM ----------------
// MODE 1: A = (1+eps)*HIN[n] + sum_{CSC} HIN[src]  (fused gather, 2-way MLP),
//         out -> Y1, stats slot0; block0 zeroes slot1.
// MODE 2: A = relu(bn1(Y1)) with BN1 finalized in-block from g_stats slot0,
//         out -> P, stats slot1.
#define PAD 136
#define GEMM_SMEM 106496

template<int MODE>
__global__ void __launch_bounds__(256, 2)
k_mma(int wslot, const float* __restrict__ bias,
      const float* __restrict__ epsp,
      const float* __restrict__ bg, const float* __restrict__ bb) {
    extern __shared__ char dsm[];
    __shared__ float s_sc[HH], s_sh[HH];

    const uint32_t su = smem_u32(dsm);
    const uint32_t Ah_u = su, Al_u = su + 17408;
    const uint32_t Bh_u = su + 34816, Bl_u = su + 69632;
    __nv_bfloat16* Ah = (__nv_bfloat16*)dsm;
    __nv_bfloat16* Al = (__nv_bfloat16*)(dsm + 17408);
    __nv_bfloat16* Bh = (__nv_bfloat16*)(dsm + 34816);
    __nv_bfloat16* Bl = (__nv_bfloat16*)(dsm + 69632);
    float* sS = (float*)(dsm + 104448);   // [2][128]
    float* sQ = (float*)(dsm + 105472);   // [2][128]

    const int tid = threadIdx.x;
    const int wid = tid >> 5, lane = tid & 31;
    const int wm = wid & 1, wn = wid >> 1;
    const int m0 = blockIdx.x * 64;

    if (MODE == 1 && blockIdx.x == 0 && tid < 2 * HH)
        g_stats[2 * HH + tid] = 0.f;   // zero slot1 for upcoming GEMM2
    if (MODE == 2 && tid < HH) {
        // finalize BN1 from g_stats slot0 in-block (GEMM1 kernel fully retired)
        float mu  = g_stats[tid] * (1.f / (float)NN);
        float msq = g_stats[HH + tid] * (1.f / (float)NN);
        float rstd = rsqrtf(msq - mu * mu + 1e-5f);
        float s = __ldg(bg + tid) * rstd;
        s_sc[tid] = s;
        s_sh[tid] = __ldg(bb + tid) - s * mu;
    }
    const float epsl = (MODE == 1) ? (1.f + __ldg(epsp)) : 0.f;
    if (MODE == 2) __syncthreads();

    // ---- W [n][k] hi/lo -> smem (coalesced 16B) ----
    const __nv_bfloat16* wh = g_Wh + (size_t)wslot * HH * HH;
    const __nv_bfloat16* wl = g_Wl + (size_t)wslot * HH * HH;
#pragma unroll
    for (int it = 0; it < 8; it++) {
        int q = it * 256 + tid;
        int n = q >> 4, k0 = (q & 15) * 8;
        *(uint4*)(Bh + n * PAD + k0) = *(const uint4*)(wh + n * HH + k0);
        *(uint4*)(Bl + n * PAD + k0) = *(const uint4*)(wl + n * HH + k0);
    }
    // ---- A: load + transform + split (warp-per-row; MODE1 fuses CSC gather) ----
#pragma unroll
    for (int it = 0; it < 8; it++) {
        int q = it * 256 + tid;
        int r = q >> 5, c0 = (q & 31) * 4;   // whole warp shares r
        int grow = m0 + r;
        float4 v = make_float4(0.f, 0.f, 0.f, 0.f);
        if (grow < NN) {
            if (MODE == 1) {
                float4 hv = *(const float4*)(g_HIN + (size_t)grow * HH + c0);
                v.x = epsl * hv.x; v.y = epsl * hv.y;
                v.z = epsl * hv.z; v.w = epsl * hv.w;
                float4 v2 = make_float4(0.f, 0.f, 0.f, 0.f);
                int e0 = __ldg(&g_off2[grow]), e1 = __ldg(&g_off2[grow + 1]);
                int e = e0;
                for (; e + 2 <= e1; e += 2) {
                    int s0 = __ldg(&g_pack2[e]);
                    int s1 = __ldg(&g_pack2[e + 1]);
                    float4 a = *(const float4*)(g_HIN + (size_t)s0 * HH + c0);
                    float4 b = *(const float4*)(g_HIN + (size_t)s1 * HH + c0);
                    v.x += a.x; v.y += a.y; v.z += a.z; v.w += a.w;
                    v2.x += b.x; v2.y += b.y; v2.z += b.z; v2.w += b.w;
                }
                if (e < e1) {
                    int s0 = __ldg(&g_pack2[e]);
                    float4 a = *(const float4*)(g_HIN + (size_t)s0 * HH + c0);
                    v.x += a.x; v.y += a.y; v.z += a.z; v.w += a.w;
                }
                v.x += v2.x; v.y += v2.y; v.z += v2.z; v.w += v2.w;
            } else {
                float4 y = *(const float4*)(g_Y1 + (size_t)grow * HH + c0);
                v.x = fmaxf(fmaf(s_sc[c0 + 0], y.x, s_sh[c0 + 0]), 0.f);
                v.y = fmaxf(fmaf(s_sc[c0 + 1], y.y, s_sh[c0 + 1]), 0.f);
                v.z = fmaxf(fmaf(s_sc[c0 + 2], y.z, s_sh[c0 + 2]), 0.f);
                v.w = fmaxf(fmaf(s_sc[c0 + 3], y.w, s_sh[c0 + 3]), 0.f);
            }
        }
        float fv[4] = {v.x, v.y, v.z, v.w};
        __nv_bfloat16 hb[4], lb[4];
#pragma unroll
        for (int j = 0; j < 4; j++) {
            hb[j] = __float2bfloat16(fv[j]);
            lb[j] = __float2bfloat16(fv[j] - __bfloat162float(hb[j]));
        }
        *(uint2*)(Ah + r * PAD + c0) = *(uint2*)hb;
        *(uint2*)(Al + r * PAD + c0) = *(uint2*)lb;
    }
    __syncthreads();

    // ---- HMMA mainloop: K=128 in 8 steps of 16 ----
    float acc[2][4][4];
#pragma unroll
    for (int mi = 0; mi < 2; mi++)
#pragma unroll
        for (int nb = 0; nb < 4; nb++)
#pragma unroll
            for (int j = 0; j < 4; j++) acc[mi][nb][j] = 0.f;

    const int aRow = wm * 32 + (lane & 15);
    const int aKs = (lane >> 4) * 8;
    const int bN = wn * 32 + (lane >> 4) * 8 + (lane & 7);
    const int bKs = ((lane >> 3) & 1) * 8;

#pragma unroll
    for (int ks = 0; ks < 8; ks++) {
        uint32_t ah[2][4], al[2][4], bh[2][4], bl[2][4];
#pragma unroll
        for (int mi = 0; mi < 2; mi++) {
            uint32_t ra = (uint32_t)(((aRow + mi * 16) * PAD + ks * 16 + aKs) * 2);
            ldsm4(ah[mi], Ah_u + ra);
            ldsm4(al[mi], Al_u + ra);
        }
#pragma unroll
        for (int nb2 = 0; nb2 < 2; nb2++) {
            uint32_t rb = (uint32_t)(((bN + nb2 * 16) * PAD + ks * 16 + bKs) * 2);
            ldsm4(bh[nb2], Bh_u + rb);
            ldsm4(bl[nb2], Bl_u + rb);
        }
#pragma unroll
        for (int mi = 0; mi < 2; mi++)
#pragma unroll
            for (int nb = 0; nb < 4; nb++) {
                const uint32_t* bhp = &bh[nb >> 1][(nb & 1) * 2];
                const uint32_t* blp = &bl[nb >> 1][(nb & 1) * 2];
                mma16816(acc[mi][nb], ah[mi], bhp);
                mma16816(acc[mi][nb], ah[mi], blp);
                mma16816(acc[mi][nb], al[mi], bhp);
            }
    }

    // ---- epilogue: bias, store, per-column stats ----
    float* outp = (MODE == 1) ? g_Y1 : g_P;
    float cs[4][2], cq[4][2];
#pragma unroll
    for (int nb = 0; nb < 4; nb++) { cs[nb][0] = cs[nb][1] = 0.f; cq[nb][0] = cq[nb][1] = 0.f; }
    float bse[4][2];
#pragma unroll
    for (int nb = 0; nb < 4; nb++) {
        int c = wn * 32 + nb * 8 + (lane & 3) * 2;
        bse[nb][0] = __ldg(bias + c);
        bse[nb][1] = __ldg(bias + c + 1);
    }
#pragma unroll
    for (int mi = 0; mi < 2; mi++) {
        int r0 = m0 + wm * 32 + mi * 16 + (lane >> 2);
        int r1 = r0 + 8;
        bool v0 = r0 < NN, v1 = r1 < NN;
#pragma unroll
        for (int nb = 0; nb < 4; nb++) {
            int c = wn * 32 + nb * 8 + (lane & 3) * 2;
            float o0 = acc[mi][nb][0] + bse[nb][0];
            float o1 = acc[mi][nb][1] + bse[nb][1];
            float o2 = acc[mi][nb][2] + bse[nb][0];
            float o3 = acc[mi][nb][3] + bse[nb][1];
            if (v0) {
                *(float2*)(outp + (size_t)r0 * HH + c) = make_float2(o0, o1);
                cs[nb][0] += o0; cs[nb][1] += o1;
                cq[nb][0] += o0 * o0; cq[nb][1] += o1 * o1;
            }
            if (v1) {
                *(float2*)(outp + (size_t)r1 * HH + c) = make_float2(o2, o3);
                cs[nb][0] += o2; cs[nb][1] += o3;
                cq[nb][0] += o2 * o2; cq[nb][1] += o3 * o3;
            }
        }
    }
#pragma unroll
    for (int nb = 0; nb < 4; nb++) {
#pragma unroll
        for (int j = 0; j < 2; j++) {
            float s = cs[nb][j], q = cq[nb][j];
#pragma unroll
            for (int off = 16; off >= 4; off >>= 1) {
                s += __shfl_down_sync(0xffffffffu, s, off);
                q += __shfl_down_sync(0xffffffffu, q, off);
            }
            if (lane < 4) {
                int c = wn * 32 + nb * 8 + lane * 2 + j;
                sS[wm * HH + c] = s;
                sQ[wm * HH + c] = q;
            }
        }
    }
    __syncthreads();
    if (tid < HH) {
        float s = sS[tid] + sS[HH + tid];
        float q = sQ[tid] + sQ[HH + tid];
        float* st = g_stats + ((MODE == 1) ? 0 : 2 * HH);
        atomicAdd(st + tid, s);
        atomicAdd(st + HH + tid, q);
    }
}

// finalize BN2 (slot 1) -> g_bn slots 2,3 (consumed by k_node / k_pool)
__global__ void k_bnstat2() {
    int j = threadIdx.x;
    float s  = g_stats[2 * HH + j];
    float sq = g_stats[3 * HH + j];
    float mu = s * (1.f / (float)NN);
    float var = sq * (1.f / (float)NN) - mu * mu;
    g_bn[2 * HH + j] = mu;
    g_bn[3 * HH + j] = rsqrtf(var + 1e-5f);
}

__global__ void k_pool(const int* __restrict__ batch,
                       const float* __restrict__ bg, const float* __restrict__ bb) {
    int idx = blockIdx.x * blockDim.x + threadIdx.x;
    int n = idx >> 5; if (n >= NN) return;
    int c = (idx & 31) << 2;
    float4 y = *(const float4*)(g_P + (size_t)n * HH + c);
    float s0 = __ldg(bg + c + 0) * g_bn[3 * HH + c + 0];
    float s1 = __ldg(bg + c + 1) * g_bn[3 * HH + c + 1];
    float s2 = __ldg(bg + c + 2) * g_bn[3 * HH + c + 2];
    float s3 = __ldg(bg + c + 3) * g_bn[3 * HH + c + 3];
    float4 o;
    o.x = fmaf(s0, y.x - g_bn[2 * HH + c + 0], __ldg(bb + c + 0));
    o.y = fmaf(s1, y.y - g_bn[2 * HH + c + 1], __ldg(bb + c + 1));
    o.z = fmaf(s2, y.z - g_bn[2 * HH + c + 2], __ldg(bb + c + 2));
    o.w = fmaf(s3, y.w - g_bn[2 * HH + c + 3], __ldg(bb + c + 3));
    red_add_v4(g_pool + (size_t)__ldg(batch + n) * HH + c, o);
}

__global__ void k_final(const float* __restrict__ cw1, const float* __restrict__ cb1,
                        const float* __restrict__ cw2, const float* __restrict__ cb2,
                        float* __restrict__ out) {
    __shared__ float p[HH];
    __shared__ float rb[4];
    int j = threadIdx.x;
    p[j] = g_pool[(size_t)blockIdx.x * HH + j];
    __syncthreads();
    float acc = __ldg(cb1 + j);
#pragma unroll 8
    for (int i = 0; i < HH; i++)
        acc = fmaf(p[i], __ldg(cw1 + i * HH + j), acc);
    float v = fmaxf(acc, 0.f) * __ldg(cw2 + j);
#pragma unroll
    for (int off = 16; off > 0; off >>= 1)
        v += __shfl_down_sync(0xffffffffu, v, off);
    if ((j & 31) == 0) rb[j >> 5] = v;
    __syncthreads();
    if (j == 0) out[blockIdx.x] = rb[0] + rb[1] + rb[2] + rb[3] + __ldg(cb2);
}

extern "C" void kernel_launch(void* const* d_in, const int* in_sizes, int n_in,
                              void* d_out, int out_size) {
    const int*   x     = (const int*)d_in[0];
    const int*   ei    = (const int*)d_in[1];
    const int*   ea    = (const int*)d_in[2];
    const int*   batch = (const int*)d_in[3];
    const float* aemb  = (const float*)d_in[4];
    const float* bemb  = (const float*)d_in[5];
    const float* eps   = (const float*)d_in[6];
    const float* w1    = (const float*)d_in[7];
    const float* b1    = (const float*)d_in[8];
    const float* bn1g  = (const float*)d_in[9];
    const float* bn1b  = (const float*)d_in[10];
    const float* w2    = (const float*)d_in[11];
    const float* b2    = (const float*)d_in[12];
    const float* bng   = (const float*)d_in[13];
    const float* bnb   = (const float*)d_in[14];
    const float* cw1   = (const float*)d_in[15];
    const float* cb1   = (const float*)d_in[16];
    const float* cw2   = (const float*)d_in[17];
    const float* cb2   = (const float*)d_in[18];
    float* out = (float*)d_out;
    const int* row = ei;
    const int* col = ei + EE;

    cudaFuncSetAttribute(k_mma<1>, cudaFuncAttributeMaxDynamicSharedMemorySize, GEMM_SMEM);
    cudaFuncSetAttribute(k_mma<2>, cudaFuncAttributeMaxDynamicSharedMemorySize, GEMM_SMEM);

    const int NT = 256;
    const int gridNH = (NN * 32 + NT - 1) / NT;   // 37500
    const int gridE  = (EE + NT - 1) / NT;
    const int gridGEMM = (NN + 63) / 64;          // 4688
    const int gridNode = (NN + 7) / 8;            // 37500

    k_init<<<2048, NT>>>();
    k_prepw<<<dim3(16, 10), 256>>>(w1, w2);
    k_prepbond<<<dim3(216, 5), HH>>>(bemb);
    k_atom<<<gridNH, NT>>>(x, aemb);
    k_cnt<<<gridE, NT>>>(row, col);
    k_scan<<<2, 1024>>>();
    k_fill<<<gridE, NT>>>(row, col, ea);
    for (int l = 0; l < 5; l++) {
        if (l == 0)
            k_node<1><<<gridNode, NT>>>(0, nullptr, nullptr);
        else
            k_node<0><<<gridNode, NT>>>(l, bng + (l - 1) * HH, bnb + (l - 1) * HH);
        k_mma<1><<<gridGEMM, NT, GEMM_SMEM>>>(2 * l, b1 + l * HH, eps + l, nullptr, nullptr);
        k_mma<2><<<gridGEMM, NT, GEMM_SMEM>>>(2 * l + 1, b2 + l * HH, nullptr,
                                              bn1g + l * HH, bn1b + l * HH);
        k_bnstat2<<<1, HH>>>();
    }
    k_pool<<<gridNH, NT>>>(batch, bng + 4 * HH, bnb + 4 * HH);
    k_final<<<GG, HH>>>(cw1, cb1, cw2, cb2, out);
}

// round 9
// speedup vs baseline: 1.1310x; 1.1310x over previous
#include <cuda_runtime.h>
#include <cuda_bf16.h>
#include <cstdint>

#define NN 300000
#define EE 600000
#define HH 128
#define GG 8192

// ---------------- scratch (device globals: allocation-free) ----------------
__device__ float g_P[(size_t)NN * HH];    // prev-layer raw output (y2 pre-BN)
__device__ float g_HIN[(size_t)NN * HH];  // h_in
__device__ float g_Y1[(size_t)NN * HH];   // y1 (pre-BN1 GEMM1 output)
__device__ float g_pool[(size_t)GG * HH];
__device__ float g_stats[4 * HH];         // [sum1, sumsq1 | sum2, sumsq2]
__device__ __nv_bfloat16 g_Wh[10 * HH * HH];
__device__ __nv_bfloat16 g_Wl[10 * HH * HH];
// CSR by row (payload cidx) for bond sums; CSC by col (payload row) for aggr gather
__device__ int g_cnt[NN],  g_cur[NN],  g_off[NN + 1];
__device__ int g_cnt2[NN], g_cur2[NN], g_off2[NN + 1];
__device__ unsigned int g_pack[EE];    // cidx (bond table index)
__device__ int g_pack2[EE];            // src row
// precombined bond tables: [5][216][128]
__device__ float g_ctab[5 * 216 * HH];

__device__ __forceinline__ void red_add_v4(float* p, float4 v) {
    asm volatile("red.global.add.v4.f32 [%0], {%1,%2,%3,%4};"
                 :: "l"(p), "f"(v.x), "f"(v.y), "f"(v.z), "f"(v.w) : "memory");
}
__device__ __forceinline__ uint32_t smem_u32(const void* p) {
    uint32_t a;
    asm("{ .reg .u64 t; cvta.to.shared.u64 t, %1; cvt.u32.u64 %0, t; }" : "=r"(a) : "l"(p));
    return a;
}
__device__ __forceinline__ void ldsm4(uint32_t* r, uint32_t addr) {
    asm volatile("ldmatrix.sync.aligned.m8n8.x4.shared.b16 {%0,%1,%2,%3}, [%4];"
                 : "=r"(r[0]), "=r"(r[1]), "=r"(r[2]), "=r"(r[3]) : "r"(addr));
}
__device__ __forceinline__ void mma16816(float* d, const uint32_t* a, const uint32_t* b) {
    asm volatile("mma.sync.aligned.m16n8k16.row.col.f32.bf16.bf16.f32 "
                 "{%0,%1,%2,%3}, {%4,%5,%6,%7}, {%8,%9}, {%0,%1,%2,%3};"
                 : "+f"(d[0]), "+f"(d[1]), "+f"(d[2]), "+f"(d[3])
                 : "r"(a[0]), "r"(a[1]), "r"(a[2]), "r"(a[3]), "r"(b[0]), "r"(b[1]));
}

// ---------------- setup kernels ----------------
__global__ void k_init() {
    size_t stride = (size_t)gridDim.x * blockDim.x;
    size_t i0 = (size_t)blockIdx.x * blockDim.x + threadIdx.x;
    for (size_t i = i0; i < (size_t)NN; i += stride) {
        g_cnt[i] = 0; g_cur[i] = 0; g_cnt2[i] = 0; g_cur2[i] = 0;
    }
    for (size_t i = i0; i < (size_t)GG * HH; i += stride) g_pool[i] = 0.f;
}

__global__ void k_prepw(const float* __restrict__ w1, const float* __restrict__ w2) {
    int l = blockIdx.y;   // 0..9
    const float* W = (l < 5) ? (w1 + (size_t)l * HH * HH) : (w2 + (size_t)(l - 5) * HH * HH);
    int slot = (l < 5) ? (2 * l) : (2 * (l - 5) + 1);
    int q = blockIdx.x * 256 + threadIdx.x;
    int k = q >> 5, n0 = (q & 31) * 4;
    float4 w = *(const float4*)(W + (size_t)k * HH + n0);
    float wv[4] = {w.x, w.y, w.z, w.w};
#pragma unroll
    for (int j = 0; j < 4; j++) {
        __nv_bfloat16 h = __float2bfloat16(wv[j]);
        size_t o = (size_t)slot * HH * HH + (size_t)(n0 + j) * HH + k;
        g_Wh[o] = h;
        g_Wl[o] = __float2bfloat16(wv[j] - __bfloat162float(h));
    }
}

__global__ void k_prepbond(const float* __restrict__ bemb) {
    int c = blockIdx.x;   // 0..215
    int l = blockIdx.y;   // 0..4
    int h = threadIdx.x;  // 0..127
    int a0 = c / 36, a1 = (c / 6) % 6, a2 = c % 6;
    const float* b = bemb + (size_t)l * 3 * 8 * HH;
    g_ctab[((size_t)l * 216 + c) * HH + h] =
        b[(size_t)(0 * 8 + a0) * HH + h] + b[(size_t)(1 * 8 + a1) * HH + h]
        + b[(size_t)(2 * 8 + a2) * HH + h];
}

__global__ void k_cnt(const int* __restrict__ row, const int* __restrict__ col) {
    int e = blockIdx.x * blockDim.x + threadIdx.x;
    if (e < EE) {
        atomicAdd(&g_cnt[__ldg(row + e)], 1);
        atomicAdd(&g_cnt2[__ldg(col + e)], 1);
    }
}

// exclusive scan: block 0 -> (cnt,off), block 1 -> (cnt2,off2)
__global__ void k_scan() {
    __shared__ int bs[1024];
    const int* cnt = (blockIdx.x == 0) ? g_cnt : g_cnt2;
    int* off = (blockIdx.x == 0) ? g_off : g_off2;
    const int t = threadIdx.x;
    const int C = (NN + 1023) / 1024;   // 293
    int base = t * C;
    int s = 0;
    for (int i = 0; i < C; i++) {
        int idx = base + i;
        if (idx < NN) s += cnt[idx];
    }
    bs[t] = s;
    __syncthreads();
    for (int o = 1; o < 1024; o <<= 1) {
        int u = (t >= o) ? bs[t - o] : 0;
        __syncthreads();
        bs[t] += u;
        __syncthreads();
    }
    int run = bs[t] - s;
    for (int i = 0; i < C; i++) {
        int idx = base + i;
        if (idx < NN) { off[idx] = run; run += cnt[idx]; }
    }
    if (t == 1023) off[NN] = EE;
}

__global__ void k_fill(const int* __restrict__ row, const int* __restrict__ col,
                       const int* __restrict__ eattr) {
    int e = blockIdx.x * blockDim.x + threadIdx.x;
    if (e >= EE) return;
    int r = __ldg(row + e);
    int c = __ldg(col + e);
    int a0 = __ldg(eattr + e * 3 + 0);
    int a1 = __ldg(eattr + e * 3 + 1);
    int a2 = __ldg(eattr + e * 3 + 2);
    int pos = g_off[r] + atomicAdd(&g_cur[r], 1);
    g_pack[pos] = (unsigned int)(a0 * 36 + a1 * 6 + a2);
    int pos2 = g_off2[c] + atomicAdd(&g_cur2[c], 1);
    g_pack2[pos2] = r;
}

// ---------------- node kernel (bond sum + act(prev) + hin) ----------------
// warp per node; block 0 zeroes stats slot0 for upcoming GEMM1.
// FIRST=1: act(prev) = AtomEncoder computed in-place (P never materialized).
// FIRST=0: act(prev) = relu(bn2(P)), BN2 finalized per-block from g_stats slot1.
template<int FIRST>
__global__ void __launch_bounds__(256)
k_node(int layer, const float* __restrict__ bg, const float* __restrict__ bb,
       const int* __restrict__ x, const float* __restrict__ aemb) {
    __shared__ float s_sc[HH], s_sh[HH];
    const int tid = threadIdx.x;
    if (blockIdx.x == 0 && tid < 2 * HH) g_stats[tid] = 0.f;   // zero slot0
    if (!FIRST) {
        if (tid < HH) {
            float mu  = g_stats[2 * HH + tid] * (1.f / (float)NN);
            float msq = g_stats[3 * HH + tid] * (1.f / (float)NN);
            float rstd = rsqrtf(msq - mu * mu + 1e-5f);
            float s = __ldg(bg + tid) * rstd;
            s_sc[tid] = s;
            s_sh[tid] = __ldg(bb + tid) - s * mu;
        }
        __syncthreads();
    }
    const int n = blockIdx.x * 8 + (tid >> 5);
    if (n >= NN) return;
    const int c4 = (tid & 31) << 2;
    const float* ctab = g_ctab + (size_t)layer * 216 * HH;
    const int e0 = __ldg(&g_off[n]), e1 = __ldg(&g_off[n + 1]);
    const float inv = 1.f / ((float)(e1 - e0) + 1.f);

    float4 bsum = make_float4(0.f, 0.f, 0.f, 0.f);
    for (int e = e0; e < e1; e++) {
        unsigned int ci = __ldg(&g_pack[e]);
        const float4 t = *(const float4*)(ctab + (size_t)ci * HH + c4);
        bsum.x += t.x; bsum.y += t.y; bsum.z += t.z; bsum.w += t.w;
    }
    float4 p;
    if (FIRST) {
        p = make_float4(0.f, 0.f, 0.f, 0.f);
#pragma unroll
        for (int f = 0; f < 9; f++) {
            int xi = __ldg(x + n * 9 + f);
            const float4 e = *(const float4*)(aemb + ((size_t)(f * 128 + xi) * HH + c4));
            p.x += e.x; p.y += e.y; p.z += e.z; p.w += e.w;
        }
    } else {
        p = *(const float4*)(g_P + (size_t)n * HH + c4);
        p.x = fmaxf(fmaf(s_sc[c4 + 0], p.x, s_sh[c4 + 0]), 0.f);
        p.y = fmaxf(fmaf(s_sc[c4 + 1], p.y, s_sh[c4 + 1]), 0.f);
        p.z = fmaxf(fmaf(s_sc[c4 + 2], p.z, s_sh[c4 + 2]), 0.f);
        p.w = fmaxf(fmaf(s_sc[c4 + 3], p.w, s_sh[c4 + 3]), 0.f);
    }
    float4 h;
    h.x = fmaf(bsum.x, inv, p.x);
    h.y = fmaf(bsum.y, inv, p.y);
    h.z = fmaf(bsum.z, inv, p.z);
    h.w = fmaf(bsum.w, inv, p.w);
    *(float4*)(g_HIN + (size_t)n * HH + c4) = h;
}

// ---------------- HMMA bf16-split GEMM, M-tile 64, 2 CTAs/SM ----------------
// MODE 1: A = (1+eps)*HIN[n] + sum_{CSC} HIN[src]  (cross-row-parallel gather),
//         out -> Y1, stats slot0; block0 zeroes slot1.
// MODE 2: A = relu(bn1(Y1)), BN1 finalized per-block from g_stats slot0,
//         out -> P, stats slot1.
#define PAD 136
#define GEMM_SMEM 106496

template<int MODE>
__global__ void __launch_bounds__(256, 2)
k_mma(int wslot, const float* __restrict__ bias,
      const float* __restrict__ epsp,
      const float* __restrict__ bg, const float* __restrict__ bb) {
    extern __shared__ char dsm[];
    __shared__ float s_sc[HH], s_sh[HH];

    const uint32_t su = smem_u32(dsm);
    const uint32_t Ah_u = su, Al_u = su + 17408;
    const uint32_t Bh_u = su + 34816, Bl_u = su + 69632;
    __nv_bfloat16* Ah = (__nv_bfloat16*)dsm;
    __nv_bfloat16* Al = (__nv_bfloat16*)(dsm + 17408);
    __nv_bfloat16* Bh = (__nv_bfloat16*)(dsm + 34816);
    __nv_bfloat16* Bl = (__nv_bfloat16*)(dsm + 69632);
    float* sS = (float*)(dsm + 104448);   // [2][128]
    float* sQ = (float*)(dsm + 105472);   // [2][128]

    const int tid = threadIdx.x;
    const int wid = tid >> 5, lane = tid & 31;
    const int wm = wid & 1, wn = wid >> 1;
    const int m0 = blockIdx.x * 64;

    if (MODE == 1 && blockIdx.x == 0 && tid < 2 * HH)
        g_stats[2 * HH + tid] = 0.f;   // zero slot1 for upcoming GEMM2
    if (MODE == 2 && tid < HH) {
        float mu  = g_stats[tid] * (1.f / (float)NN);
        float msq = g_stats[HH + tid] * (1.f / (float)NN);
        float rstd = rsqrtf(msq - mu * mu + 1e-5f);
        float s = __ldg(bg + tid) * rstd;
        s_sc[tid] = s;
        s_sh[tid] = __ldg(bb + tid) - s * mu;
    }
    const float epsl = (MODE == 1) ? (1.f + __ldg(epsp)) : 0.f;
    if (MODE == 2) __syncthreads();

    // ---- W [n][k] hi/lo -> smem (coalesced 16B) ----
    const __nv_bfloat16* wh = g_Wh + (size_t)wslot * HH * HH;
    const __nv_bfloat16* wl = g_Wl + (size_t)wslot * HH * HH;
#pragma unroll
    for (int it = 0; it < 8; it++) {
        int q = it * 256 + tid;
        int n = q >> 4, k0 = (q & 15) * 8;
        *(uint4*)(Bh + n * PAD + k0) = *(const uint4*)(wh + n * HH + k0);
        *(uint4*)(Bl + n * PAD + k0) = *(const uint4*)(wl + n * HH + k0);
    }

    // ---- A: load + transform + split ----
    const int w = tid >> 5;
    const int c0 = (tid & 31) * 4;
    if (MODE == 1) {
        // two groups of 4 rows; within a group all loads are independent (MLP)
#pragma unroll
        for (int g = 0; g < 2; g++) {
            int rg[4], ea[4], eb[4];
#pragma unroll
            for (int i = 0; i < 4; i++) {
                rg[i] = m0 + (g * 4 + i) * 8 + w;
                bool ok = rg[i] < NN;
                ea[i] = ok ? __ldg(&g_off2[rg[i]]) : 0;
                eb[i] = ok ? __ldg(&g_off2[rg[i] + 1]) : 0;
            }
            // speculative first-4 neighbor indices per row (independent batch)
            int src[4][4];
#pragma unroll
            for (int i = 0; i < 4; i++) {
                int d = eb[i] - ea[i];
#pragma unroll
                for (int j = 0; j < 4; j++) {
                    int idx = ea[i] + ((j < d) ? j : 0);
                    src[i][j] = (d > 0) ? __ldg(&g_pack2[idx]) : 0;
                }
            }
            float4 vv[4];
#pragma unroll
            for (int i = 0; i < 4; i++) {
                float4 v = make_float4(0.f, 0.f, 0.f, 0.f);
                if (rg[i] < NN) {
                    float4 hv = *(const float4*)(g_HIN + (size_t)rg[i] * HH + c0);
                    v.x = epsl * hv.x; v.y = epsl * hv.y;
                    v.z = epsl * hv.z; v.w = epsl * hv.w;
                }
                vv[i] = v;
            }
            // parallel gathers (up to 16 independent loads)
#pragma unroll
            for (int j = 0; j < 4; j++) {
#pragma unroll
                for (int i = 0; i < 4; i++) {
                    if (j < eb[i] - ea[i]) {
                        float4 a = *(const float4*)(g_HIN + (size_t)src[i][j] * HH + c0);
                        vv[i].x += a.x; vv[i].y += a.y;
                        vv[i].z += a.z; vv[i].w += a.w;
                    }
                }
            }
            // rare tails (deg > 4)
#pragma unroll
            for (int i = 0; i < 4; i++) {
                for (int e = ea[i] + 4; e < eb[i]; e++) {
                    int s0 = __ldg(&g_pack2[e]);
                    float4 a = *(const float4*)(g_HIN + (size_t)s0 * HH + c0);
                    vv[i].x += a.x; vv[i].y += a.y;
                    vv[i].z += a.z; vv[i].w += a.w;
                }
            }
            // split + store to smem
#pragma unroll
            for (int i = 0; i < 4; i++) {
                int r = (g * 4 + i) * 8 + w;
                float fv[4] = {vv[i].x, vv[i].y, vv[i].z, vv[i].w};
                __nv_bfloat16 hb[4], lb[4];
#pragma unroll
                for (int j = 0; j < 4; j++) {
                    hb[j] = __float2bfloat16(fv[j]);
                    lb[j] = __float2bfloat16(fv[j] - __bfloat162float(hb[j]));
                }
                *(uint2*)(Ah + r * PAD + c0) = *(uint2*)hb;
                *(uint2*)(Al + r * PAD + c0) = *(uint2*)lb;
            }
        }
    } else {
#pragma unroll
        for (int it = 0; it < 8; it++) {
            int r = it * 8 + w;
            int grow = m0 + r;
            float4 v = make_float4(0.f, 0.f, 0.f, 0.f);
            if (grow < NN) {
                float4 y = *(const float4*)(g_Y1 + (size_t)grow * HH + c0);
                v.x = fmaxf(fmaf(s_sc[c0 + 0], y.x, s_sh[c0 + 0]), 0.f);
                v.y = fmaxf(fmaf(s_sc[c0 + 1], y.y, s_sh[c0 + 1]), 0.f);
                v.z = fmaxf(fmaf(s_sc[c0 + 2], y.z, s_sh[c0 + 2]), 0.f);
                v.w = fmaxf(fmaf(s_sc[c0 + 3], y.w, s_sh[c0 + 3]), 0.f);
            }
            float fv[4] = {v.x, v.y, v.z, v.w};
            __nv_bfloat16 hb[4], lb[4];
#pragma unroll
            for (int j = 0; j < 4; j++) {
                hb[j] = __float2bfloat16(fv[j]);
                lb[j] = __float2bfloat16(fv[j] - __bfloat162float(hb[j]));
            }
            *(uint2*)(Ah + r * PAD + c0) = *(uint2*)hb;
            *(uint2*)(Al + r * PAD + c0) = *(uint2*)lb;
        }
    }
    __syncthreads();

    // ---- HMMA mainloop: K=128 in 8 steps of 16 ----
    float acc[2][4][4];
#pragma unroll
    for (int mi = 0; mi < 2; mi++)
#pragma unroll
        for (int nb = 0; nb < 4; nb++)
#pragma unroll
            for (int j = 0; j < 4; j++) acc[mi][nb][j] = 0.f;

    const int aRow = wm * 32 + (lane & 15);
    const int aKs = (lane >> 4) * 8;
    const int bN = wn * 32 + (lane >> 4) * 8 + (lane & 7);
    const int bKs = ((lane >> 3) & 1) * 8;

#pragma unroll
    for (int ks = 0; ks < 8; ks++) {
        uint32_t ah[2][4], al[2][4], bh[2][4], bl[2][4];
#pragma unroll
        for (int mi = 0; mi < 2; mi++) {
            uint32_t ra = (uint32_t)(((aRow + mi * 16) * PAD + ks * 16 + aKs) * 2);
            ldsm4(ah[mi], Ah_u + ra);
            ldsm4(al[mi], Al_u + ra);
        }
#pragma unroll
        for (int nb2 = 0; nb2 < 2; nb2++) {
            uint32_t rb = (uint32_t)(((bN + nb2 * 16) * PAD + ks * 16 + bKs) * 2);
            ldsm4(bh[nb2], Bh_u + rb);
            ldsm4(bl[nb2], Bl_u + rb);
        }
#pragma unroll
        for (int mi = 0; mi < 2; mi++)
#pragma unroll
            for (int nb = 0; nb < 4; nb++) {
                const uint32_t* bhp = &bh[nb >> 1][(nb & 1) * 2];
                const uint32_t* blp = &bl[nb >> 1][(nb & 1) * 2];
                mma16816(acc[mi][nb], ah[mi], bhp);
                mma16816(acc[mi][nb], ah[mi], blp);
                mma16816(acc[mi][nb], al[mi], bhp);
            }
    }

    // ---- epilogue: bias, store, per-column stats ----
    float* outp = (MODE == 1) ? g_Y1 : g_P;
    float cs[4][2], cq[4][2];
#pragma unroll
    for (int nb = 0; nb < 4; nb++) { cs[nb][0] = cs[nb][1] = 0.f; cq[nb][0] = cq[nb][1] = 0.f; }
    float bse[4][2];
#pragma unroll
    for (int nb = 0; nb < 4; nb++) {
        int c = wn * 32 + nb * 8 + (lane & 3) * 2;
        bse[nb][0] = __ldg(bias + c);
        bse[nb][1] = __ldg(bias + c + 1);
    }
#pragma unroll
    for (int mi = 0; mi < 2; mi++) {
        int r0 = m0 + wm * 32 + mi * 16 + (lane >> 2);
        int r1 = r0 + 8;
        bool v0 = r0 < NN, v1 = r1 < NN;
#pragma unroll
        for (int nb = 0; nb < 4; nb++) {
            int c = wn * 32 + nb * 8 + (lane & 3) * 2;
            float o0 = acc[mi][nb][0] + bse[nb][0];
            float o1 = acc[mi][nb][1] + bse[nb][1];
            float o2 = acc[mi][nb][2] + bse[nb][0];
            float o3 = acc[mi][nb][3] + bse[nb][1];
            if (v0) {
                *(float2*)(outp + (size_t)r0 * HH + c) = make_float2(o0, o1);
                cs[nb][0] += o0; cs[nb][1] += o1;
                cq[nb][0] += o0 * o0; cq[nb][1] += o1 * o1;
            }
            if (v1) {
                *(float2*)(outp + (size_t)r1 * HH + c) = make_float2(o2, o3);
                cs[nb][0] += o2; cs[nb][1] += o3;
                cq[nb][0] += o2 * o2; cq[nb][1] += o3 * o3;
            }
        }
    }
#pragma unroll
    for (int nb = 0; nb < 4; nb++) {
#pragma unroll
        for (int j = 0; j < 2; j++) {
            float s = cs[nb][j], q = cq[nb][j];
#pragma unroll
            for (int off = 16; off >= 4; off >>= 1) {
                s += __shfl_down_sync(0xffffffffu, s, off);
                q += __shfl_down_sync(0xffffffffu, q, off);
            }
            if (lane < 4) {
                int c = wn * 32 + nb * 8 + lane * 2 + j;
                sS[wm * HH + c] = s;
                sQ[wm * HH + c] = q;
            }
        }
    }
    __syncthreads();
    if (tid < HH) {
        float s = sS[tid] + sS[HH + tid];
        float q = sQ[tid] + sQ[HH + tid];
        float* st = g_stats + ((MODE == 1) ? 0 : 2 * HH);
        atomicAdd(st + tid, s);
        atomicAdd(st + HH + tid, q);
    }
}

// pool: BN2 of last layer finalized per-block from g_stats slot1, scatter to g_pool
__global__ void __launch_bounds__(256)
k_pool(const int* __restrict__ batch,
       const float* __restrict__ bg, const float* __restrict__ bb) {
    __shared__ float s_sc[HH], s_sh[HH];
    const int tid = threadIdx.x;
    if (tid < HH) {
        float mu  = g_stats[2 * HH + tid] * (1.f / (float)NN);
        float msq = g_stats[3 * HH + tid] * (1.f / (float)NN);
        float rstd = rsqrtf(msq - mu * mu + 1e-5f);
        float s = __ldg(bg + tid) * rstd;
        s_sc[tid] = s;
        s_sh[tid] = __ldg(bb + tid) - s * mu;
    }
    __syncthreads();
    const int n = blockIdx.x * 8 + (tid >> 5);
    if (n >= NN) return;
    const int c = (tid & 31) << 2;
    float4 y = *(const float4*)(g_P + (size_t)n * HH + c);
    float4 o;
    o.x = fmaf(s_sc[c + 0], y.x, s_sh[c + 0]);
    o.y = fmaf(s_sc[c + 1], y.y, s_sh[c + 1]);
    o.z = fmaf(s_sc[c + 2], y.z, s_sh[c + 2]);
    o.w = fmaf(s_sc[c + 3], y.w, s_sh[c + 3]);
    red_add_v4(g_pool + (size_t)__ldg(batch + n) * HH + c, o);
}

__global__ void k_final(const float* __restrict__ cw1, const float* __restrict__ cb1,
                        const float* __restrict__ cw2, const float* __restrict__ cb2,
                        float* __restrict__ out) {
    __shared__ float p[HH];
    __shared__ float rb[4];
    int j = threadIdx.x;
    p[j] = g_pool[(size_t)blockIdx.x * HH + j];
    __syncthreads();
    float acc = __ldg(cb1 + j);
#pragma unroll 8
    for (int i = 0; i < HH; i++)
        acc = fmaf(p[i], __ldg(cw1 + i * HH + j), acc);
    float v = fmaxf(acc, 0.f) * __ldg(cw2 + j);
#pragma unroll
    for (int off = 16; off > 0; off >>= 1)
        v += __shfl_down_sync(0xffffffffu, v, off);
    if ((j & 31) == 0) rb[j >> 5] = v;
    __syncthreads();
    if (j == 0) out[blockIdx.x] = rb[0] + rb[1] + rb[2] + rb[3] + __ldg(cb2);
}

extern "C" void kernel_launch(void* const* d_in, const int* in_sizes, int n_in,
                              void* d_out, int out_size) {
    const int*   x     = (const int*)d_in[0];
    const int*   ei    = (const int*)d_in[1];
    const int*   ea    = (const int*)d_in[2];
    const int*   batch = (const int*)d_in[3];
    const float* aemb  = (const float*)d_in[4];
    const float* bemb  = (const float*)d_in[5];
    const float* eps   = (const float*)d_in[6];
    const float* w1    = (const float*)d_in[7];
    const float* b1    = (const float*)d_in[8];
    const float* bn1g  = (const float*)d_in[9];
    const float* bn1b  = (const float*)d_in[10];
    const float* w2    = (const float*)d_in[11];
    const float* b2    = (const float*)d_in[12];
    const float* bng   = (const float*)d_in[13];
    const float* bnb   = (const float*)d_in[14];
    const float* cw1   = (const float*)d_in[15];
    const float* cb1   = (const float*)d_in[16];
    const float* cw2   = (const float*)d_in[17];
    const float* cb2   = (const float*)d_in[18];
    float* out = (float*)d_out;
    const int* row = ei;
    const int* col = ei + EE;

    cudaFuncSetAttribute(k_mma<1>, cudaFuncAttributeMaxDynamicSharedMemorySize, GEMM_SMEM);
    cudaFuncSetAttribute(k_mma<2>, cudaFuncAttributeMaxDynamicSharedMemorySize, GEMM_SMEM);

    const int NT = 256;
    const int gridE  = (EE + NT - 1) / NT;
    const int gridGEMM = (NN + 63) / 64;          // 4688
    const int gridNode = (NN + 7) / 8;            // 37500

    k_init<<<2048, NT>>>();
    k_prepw<<<dim3(16, 10), 256>>>(w1, w2);
    k_prepbond<<<dim3(216, 5), HH>>>(bemb);
    k_cnt<<<gridE, NT>>>(row, col);
    k_scan<<<2, 1024>>>();
    k_fill<<<gridE, NT>>>(row, col, ea);
    for (int l = 0; l < 5; l++) {
        if (l == 0)
            k_node<1><<<gridNode, NT>>>(0, nullptr, nullptr, x, aemb);
        else
            k_node<0><<<gridNode, NT>>>(l, bng + (l - 1) * HH, bnb + (l - 1) * HH,
                                        nullptr, nullptr);
        k_mma<1><<<gridGEMM, NT, GEMM_SMEM>>>(2 * l, b1 + l * HH, eps + l, nullptr, nullptr);
        k_mma<2><<<gridGEMM, NT, GEMM_SMEM>>>(2 * l + 1, b2 + l * HH, nullptr,
                                              bn1g + l * HH, bn1b + l * HH);
    }
    k_pool<<<gridNode, NT>>>(batch, bng + 4 * HH, bnb + 4 * HH);
    k_final<<<GG, HH>>>(cw1, cb1, cw2, cb2, out);
}

// round 10
// speedup vs baseline: 1.2539x; 1.1086x over previous
#include <cuda_runtime.h>
#include <cuda_bf16.h>
#include <cstdint>

#define NN 300000
#define EE 600000
#define HH 128
#define GG 8192

// ---------------- scratch (device globals: allocation-free) ----------------
__device__ float g_P[(size_t)NN * HH];    // prev-layer raw output (y2 pre-BN)
__device__ float g_HIN[(size_t)NN * HH];  // h_in
__device__ float g_Y1[(size_t)NN * HH];   // y1 (pre-BN1 GEMM1 output)
__device__ float g_pool[(size_t)GG * HH];
__device__ float g_stats[4 * HH];         // [sum1, sumsq1 | sum2, sumsq2]
__device__ __nv_bfloat16 g_Wh[10 * HH * HH];
__device__ __nv_bfloat16 g_Wl[10 * HH * HH];
// CSR by row (payload cidx) for bond sums; CSC by col (payload row) for aggr gather
__device__ int g_cnt[NN],  g_cur[NN],  g_off[NN + 1];
__device__ int g_cnt2[NN], g_cur2[NN], g_off2[NN + 1];
__device__ unsigned int g_pack[EE];    // cidx (bond table index)
__device__ int g_pack2[EE];            // src row
// precombined bond tables: [5][216][128]
__device__ float g_ctab[5 * 216 * HH];

__device__ __forceinline__ void red_add_v4(float* p, float4 v) {
    asm volatile("red.global.add.v4.f32 [%0], {%1,%2,%3,%4};"
                 :: "l"(p), "f"(v.x), "f"(v.y), "f"(v.z), "f"(v.w) : "memory");
}
__device__ __forceinline__ uint32_t smem_u32(const void* p) {
    uint32_t a;
    asm("{ .reg .u64 t; cvta.to.shared.u64 t, %1; cvt.u32.u64 %0, t; }" : "=r"(a) : "l"(p));
    return a;
}
__device__ __forceinline__ void ldsm4(uint32_t* r, uint32_t addr) {
    asm volatile("ldmatrix.sync.aligned.m8n8.x4.shared.b16 {%0,%1,%2,%3}, [%4];"
                 : "=r"(r[0]), "=r"(r[1]), "=r"(r[2]), "=r"(r[3]) : "r"(addr));
}
__device__ __forceinline__ void mma16816(float* d, const uint32_t* a, const uint32_t* b) {
    asm volatile("mma.sync.aligned.m16n8k16.row.col.f32.bf16.bf16.f32 "
                 "{%0,%1,%2,%3}, {%4,%5,%6,%7}, {%8,%9}, {%0,%1,%2,%3};"
                 : "+f"(d[0]), "+f"(d[1]), "+f"(d[2]), "+f"(d[3])
                 : "r"(a[0]), "r"(a[1]), "r"(a[2]), "r"(a[3]), "r"(b[0]), "r"(b[1]));
}

// ---------------- setup kernels ----------------
__global__ void k_init() {
    size_t stride = (size_t)gridDim.x * blockDim.x;
    size_t i0 = (size_t)blockIdx.x * blockDim.x + threadIdx.x;
    for (size_t i = i0; i < (size_t)NN; i += stride) {
        g_cnt[i] = 0; g_cur[i] = 0; g_cnt2[i] = 0; g_cur2[i] = 0;
    }
    for (size_t i = i0; i < (size_t)GG * HH; i += stride) g_pool[i] = 0.f;
}

__global__ void k_prepw(const float* __restrict__ w1, const float* __restrict__ w2) {
    int l = blockIdx.y;   // 0..9
    const float* W = (l < 5) ? (w1 + (size_t)l * HH * HH) : (w2 + (size_t)(l - 5) * HH * HH);
    int slot = (l < 5) ? (2 * l) : (2 * (l - 5) + 1);
    int q = blockIdx.x * 256 + threadIdx.x;
    int k = q >> 5, n0 = (q & 31) * 4;
    float4 w = *(const float4*)(W + (size_t)k * HH + n0);
    float wv[4] = {w.x, w.y, w.z, w.w};
#pragma unroll
    for (int j = 0; j < 4; j++) {
        __nv_bfloat16 h = __float2bfloat16(wv[j]);
        size_t o = (size_t)slot * HH * HH + (size_t)(n0 + j) * HH + k;
        g_Wh[o] = h;
        g_Wl[o] = __float2bfloat16(wv[j] - __bfloat162float(h));
    }
}

__global__ void k_prepbond(const float* __restrict__ bemb) {
    int c = blockIdx.x;   // 0..215
    int l = blockIdx.y;   // 0..4
    int h = threadIdx.x;  // 0..127
    int a0 = c / 36, a1 = (c / 6) % 6, a2 = c % 6;
    const float* b = bemb + (size_t)l * 3 * 8 * HH;
    g_ctab[((size_t)l * 216 + c) * HH + h] =
        b[(size_t)(0 * 8 + a0) * HH + h] + b[(size_t)(1 * 8 + a1) * HH + h]
        + b[(size_t)(2 * 8 + a2) * HH + h];
}

__global__ void k_cnt(const int* __restrict__ row, const int* __restrict__ col) {
    int e = blockIdx.x * blockDim.x + threadIdx.x;
    if (e < EE) {
        atomicAdd(&g_cnt[__ldg(row + e)], 1);
        atomicAdd(&g_cnt2[__ldg(col + e)], 1);
    }
}

// exclusive scan: block 0 -> (cnt,off), block 1 -> (cnt2,off2)
__global__ void k_scan() {
    __shared__ int bs[1024];
    const int* cnt = (blockIdx.x == 0) ? g_cnt : g_cnt2;
    int* off = (blockIdx.x == 0) ? g_off : g_off2;
    const int t = threadIdx.x;
    const int C = (NN + 1023) / 1024;   // 293
    int base = t * C;
    int s = 0;
    for (int i = 0; i < C; i++) {
        int idx = base + i;
        if (idx < NN) s += cnt[idx];
    }
    bs[t] = s;
    __syncthreads();
    for (int o = 1; o < 1024; o <<= 1) {
        int u = (t >= o) ? bs[t - o] : 0;
        __syncthreads();
        bs[t] += u;
        __syncthreads();
    }
    int run = bs[t] - s;
    for (int i = 0; i < C; i++) {
        int idx = base + i;
        if (idx < NN) { off[idx] = run; run += cnt[idx]; }
    }
    if (t == 1023) off[NN] = EE;
}

__global__ void k_fill(const int* __restrict__ row, const int* __restrict__ col,
                       const int* __restrict__ eattr) {
    int e = blockIdx.x * blockDim.x + threadIdx.x;
    if (e >= EE) return;
    int r = __ldg(row + e);
    int c = __ldg(col + e);
    int a0 = __ldg(eattr + e * 3 + 0);
    int a1 = __ldg(eattr + e * 3 + 1);
    int a2 = __ldg(eattr + e * 3 + 2);
    int pos = g_off[r] + atomicAdd(&g_cur[r], 1);
    g_pack[pos] = (unsigned int)(a0 * 36 + a1 * 6 + a2);
    int pos2 = g_off2[c] + atomicAdd(&g_cur2[c], 1);
    g_pack2[pos2] = r;
}

// ---------------- node kernel (bond sum + act(prev) + hin) ----------------
template<int FIRST>
__global__ void __launch_bounds__(256)
k_node(int layer, const float* __restrict__ bg, const float* __restrict__ bb,
       const int* __restrict__ x, const float* __restrict__ aemb) {
    __shared__ float s_sc[HH], s_sh[HH];
    const int tid = threadIdx.x;
    if (blockIdx.x == 0 && tid < 2 * HH) g_stats[tid] = 0.f;   // zero slot0
    if (!FIRST) {
        if (tid < HH) {
            float mu  = g_stats[2 * HH + tid] * (1.f / (float)NN);
            float msq = g_stats[3 * HH + tid] * (1.f / (float)NN);
            float rstd = rsqrtf(msq - mu * mu + 1e-5f);
            float s = __ldg(bg + tid) * rstd;
            s_sc[tid] = s;
            s_sh[tid] = __ldg(bb + tid) - s * mu;
        }
        __syncthreads();
    }
    const int n = blockIdx.x * 8 + (tid >> 5);
    if (n >= NN) return;
    const int c4 = (tid & 31) << 2;
    const float* ctab = g_ctab + (size_t)layer * 216 * HH;
    const int e0 = __ldg(&g_off[n]), e1 = __ldg(&g_off[n + 1]);
    const float inv = 1.f / ((float)(e1 - e0) + 1.f);

    float4 bsum = make_float4(0.f, 0.f, 0.f, 0.f);
    for (int e = e0; e < e1; e++) {
        unsigned int ci = __ldg(&g_pack[e]);
        const float4 t = *(const float4*)(ctab + (size_t)ci * HH + c4);
        bsum.x += t.x; bsum.y += t.y; bsum.z += t.z; bsum.w += t.w;
    }
    float4 p;
    if (FIRST) {
        p = make_float4(0.f, 0.f, 0.f, 0.f);
#pragma unroll
        for (int f = 0; f < 9; f++) {
            int xi = __ldg(x + n * 9 + f);
            const float4 e = *(const float4*)(aemb + ((size_t)(f * 128 + xi) * HH + c4));
            p.x += e.x; p.y += e.y; p.z += e.z; p.w += e.w;
        }
    } else {
        p = *(const float4*)(g_P + (size_t)n * HH + c4);
        p.x = fmaxf(fmaf(s_sc[c4 + 0], p.x, s_sh[c4 + 0]), 0.f);
        p.y = fmaxf(fmaf(s_sc[c4 + 1], p.y, s_sh[c4 + 1]), 0.f);
        p.z = fmaxf(fmaf(s_sc[c4 + 2], p.z, s_sh[c4 + 2]), 0.f);
        p.w = fmaxf(fmaf(s_sc[c4 + 3], p.w, s_sh[c4 + 3]), 0.f);
    }
    float4 h;
    h.x = fmaf(bsum.x, inv, p.x);
    h.y = fmaf(bsum.y, inv, p.y);
    h.z = fmaf(bsum.z, inv, p.z);
    h.w = fmaf(bsum.w, inv, p.w);
    *(float4*)(g_HIN + (size_t)n * HH + c4) = h;
}

// ---------------- HMMA bf16-split GEMM, M-tile 64, two-pass B, 3 CTAs/SM ----
// pass1: B=Wh, acc += Ah*B + Al*B;  pass2: B=Wl, acc += Ah*B.
// smem: Ah(17408) Al(17408) B(34816) sS(1024) sQ(1024) = 71680
#define PAD 136
#define GEMM_SMEM 71680

template<int MODE>
__global__ void __launch_bounds__(256, 3)
k_mma(int wslot, const float* __restrict__ bias,
      const float* __restrict__ epsp,
      const float* __restrict__ bg, const float* __restrict__ bb) {
    extern __shared__ char dsm[];
    __shared__ float s_sc[HH], s_sh[HH];

    const uint32_t su = smem_u32(dsm);
    const uint32_t Ah_u = su, Al_u = su + 17408;
    const uint32_t B_u = su + 34816;
    __nv_bfloat16* Ah = (__nv_bfloat16*)dsm;
    __nv_bfloat16* Al = (__nv_bfloat16*)(dsm + 17408);
    __nv_bfloat16* Bs = (__nv_bfloat16*)(dsm + 34816);
    float* sS = (float*)(dsm + 69632);   // [2][128]
    float* sQ = (float*)(dsm + 70656);   // [2][128]

    const int tid = threadIdx.x;
    const int wid = tid >> 5, lane = tid & 31;
    const int wm = wid & 1, wn = wid >> 1;
    const int m0 = blockIdx.x * 64;

    if (MODE == 1 && blockIdx.x == 0 && tid < 2 * HH)
        g_stats[2 * HH + tid] = 0.f;   // zero slot1 for upcoming GEMM2
    if (MODE == 2 && tid < HH) {
        float mu  = g_stats[tid] * (1.f / (float)NN);
        float msq = g_stats[HH + tid] * (1.f / (float)NN);
        float rstd = rsqrtf(msq - mu * mu + 1e-5f);
        float s = __ldg(bg + tid) * rstd;
        s_sc[tid] = s;
        s_sh[tid] = __ldg(bb + tid) - s * mu;
    }
    const float epsl = (MODE == 1) ? (1.f + __ldg(epsp)) : 0.f;
    if (MODE == 2) __syncthreads();

    // ---- pass-1 W tile: hi ----
    const __nv_bfloat16* wh = g_Wh + (size_t)wslot * HH * HH;
    const __nv_bfloat16* wl = g_Wl + (size_t)wslot * HH * HH;
#pragma unroll
    for (int it = 0; it < 8; it++) {
        int q = it * 256 + tid;
        int n = q >> 4, k0 = (q & 15) * 8;
        *(uint4*)(Bs + n * PAD + k0) = *(const uint4*)(wh + n * HH + k0);
    }

    // ---- A: load + transform + split ----
    const int w = tid >> 5;
    const int c0 = (tid & 31) * 4;
    if (MODE == 1) {
#pragma unroll
        for (int g = 0; g < 2; g++) {
            int rg[4], ea[4], eb[4];
#pragma unroll
            for (int i = 0; i < 4; i++) {
                rg[i] = m0 + (g * 4 + i) * 8 + w;
                bool ok = rg[i] < NN;
                ea[i] = ok ? __ldg(&g_off2[rg[i]]) : 0;
                eb[i] = ok ? __ldg(&g_off2[rg[i] + 1]) : 0;
            }
            int src[4][4];
#pragma unroll
            for (int i = 0; i < 4; i++) {
                int d = eb[i] - ea[i];
#pragma unroll
                for (int j = 0; j < 4; j++) {
                    int idx = ea[i] + ((j < d) ? j : 0);
                    src[i][j] = (d > 0) ? __ldg(&g_pack2[idx]) : 0;
                }
            }
            float4 vv[4];
#pragma unroll
            for (int i = 0; i < 4; i++) {
                float4 v = make_float4(0.f, 0.f, 0.f, 0.f);
                if (rg[i] < NN) {
                    float4 hv = *(const float4*)(g_HIN + (size_t)rg[i] * HH + c0);
                    v.x = epsl * hv.x; v.y = epsl * hv.y;
                    v.z = epsl * hv.z; v.w = epsl * hv.w;
                }
                vv[i] = v;
            }
#pragma unroll
            for (int j = 0; j < 4; j++) {
#pragma unroll
                for (int i = 0; i < 4; i++) {
                    if (j < eb[i] - ea[i]) {
                        float4 a = *(const float4*)(g_HIN + (size_t)src[i][j] * HH + c0);
                        vv[i].x += a.x; vv[i].y += a.y;
                        vv[i].z += a.z; vv[i].w += a.w;
                    }
                }
            }
#pragma unroll
            for (int i = 0; i < 4; i++) {
                for (int e = ea[i] + 4; e < eb[i]; e++) {
                    int s0 = __ldg(&g_pack2[e]);
                    float4 a = *(const float4*)(g_HIN + (size_t)s0 * HH + c0);
                    vv[i].x += a.x; vv[i].y += a.y;
                    vv[i].z += a.z; vv[i].w += a.w;
                }
            }
#pragma unroll
            for (int i = 0; i < 4; i++) {
                int r = (g * 4 + i) * 8 + w;
                float fv[4] = {vv[i].x, vv[i].y, vv[i].z, vv[i].w};
                __nv_bfloat16 hb[4], lb[4];
#pragma unroll
                for (int j = 0; j < 4; j++) {
                    hb[j] = __float2bfloat16(fv[j]);
                    lb[j] = __float2bfloat16(fv[j] - __bfloat162float(hb[j]));
                }
                *(uint2*)(Ah + r * PAD + c0) = *(uint2*)hb;
                *(uint2*)(Al + r * PAD + c0) = *(uint2*)lb;
            }
        }
    } else {
#pragma unroll
        for (int it = 0; it < 8; it++) {
            int r = it * 8 + w;
            int grow = m0 + r;
            float4 v = make_float4(0.f, 0.f, 0.f, 0.f);
            if (grow < NN) {
                float4 y = *(const float4*)(g_Y1 + (size_t)grow * HH + c0);
                v.x = fmaxf(fmaf(s_sc[c0 + 0], y.x, s_sh[c0 + 0]), 0.f);
                v.y = fmaxf(fmaf(s_sc[c0 + 1], y.y, s_sh[c0 + 1]), 0.f);
                v.z = fmaxf(fmaf(s_sc[c0 + 2], y.z, s_sh[c0 + 2]), 0.f);
                v.w = fmaxf(fmaf(s_sc[c0 + 3], y.w, s_sh[c0 + 3]), 0.f);
            }
            float fv[4] = {v.x, v.y, v.z, v.w};
            __nv_bfloat16 hb[4], lb[4];
#pragma unroll
            for (int j = 0; j < 4; j++) {
                hb[j] = __float2bfloat16(fv[j]);
                lb[j] = __float2bfloat16(fv[j] - __bfloat162float(hb[j]));
            }
            *(uint2*)(Ah + r * PAD + c0) = *(uint2*)hb;
            *(uint2*)(Al + r * PAD + c0) = *(uint2*)lb;
        }
    }
    __syncthreads();

    float acc[2][4][4];
#pragma unroll
    for (int mi = 0; mi < 2; mi++)
#pragma unroll
        for (int nb = 0; nb < 4; nb++)
#pragma unroll
            for (int j = 0; j < 4; j++) acc[mi][nb][j] = 0.f;

    const int aRow = wm * 32 + (lane & 15);
    const int aKs = (lane >> 4) * 8;
    const int bN = wn * 32 + (lane >> 4) * 8 + (lane & 7);
    const int bKs = ((lane >> 3) & 1) * 8;

    // ---- pass 1: acc += Ah*Bh + Al*Bh ----
#pragma unroll
    for (int ks = 0; ks < 8; ks++) {
        uint32_t ah[2][4], al[2][4], bbq[2][4];
#pragma unroll
        for (int mi = 0; mi < 2; mi++) {
            uint32_t ra = (uint32_t)(((aRow + mi * 16) * PAD + ks * 16 + aKs) * 2);
            ldsm4(ah[mi], Ah_u + ra);
            ldsm4(al[mi], Al_u + ra);
        }
#pragma unroll
        for (int nb2 = 0; nb2 < 2; nb2++) {
            uint32_t rb = (uint32_t)(((bN + nb2 * 16) * PAD + ks * 16 + bKs) * 2);
            ldsm4(bbq[nb2], B_u + rb);
        }
#pragma unroll
        for (int mi = 0; mi < 2; mi++)
#pragma unroll
            for (int nb = 0; nb < 4; nb++) {
                const uint32_t* bp = &bbq[nb >> 1][(nb & 1) * 2];
                mma16816(acc[mi][nb], ah[mi], bp);
                mma16816(acc[mi][nb], al[mi], bp);
            }
    }
    __syncthreads();   // all warps done reading Bh

    // ---- pass-2 W tile: lo ----
#pragma unroll
    for (int it = 0; it < 8; it++) {
        int q = it * 256 + tid;
        int n = q >> 4, k0 = (q & 15) * 8;
        *(uint4*)(Bs + n * PAD + k0) = *(const uint4*)(wl + n * HH + k0);
    }
    __syncthreads();

    // ---- pass 2: acc += Ah*Bl ----
#pragma unroll
    for (int ks = 0; ks < 8; ks++) {
        uint32_t ah[2][4], bbq[2][4];
#pragma unroll
        for (int mi = 0; mi < 2; mi++) {
            uint32_t ra = (uint32_t)(((aRow + mi * 16) * PAD + ks * 16 + aKs) * 2);
            ldsm4(ah[mi], Ah_u + ra);
        }
#pragma unroll
        for (int nb2 = 0; nb2 < 2; nb2++) {
            uint32_t rb = (uint32_t)(((bN + nb2 * 16) * PAD + ks * 16 + bKs) * 2);
            ldsm4(bbq[nb2], B_u + rb);
        }
#pragma unroll
        for (int mi = 0; mi < 2; mi++)
#pragma unroll
            for (int nb = 0; nb < 4; nb++)
                mma16816(acc[mi][nb], ah[mi], &bbq[nb >> 1][(nb & 1) * 2]);
    }

    // ---- epilogue: bias, store, per-column stats ----
    float* outp = (MODE == 1) ? g_Y1 : g_P;
    float cs[4][2], cq[4][2];
#pragma unroll
    for (int nb = 0; nb < 4; nb++) { cs[nb][0] = cs[nb][1] = 0.f; cq[nb][0] = cq[nb][1] = 0.f; }
    float bse[4][2];
#pragma unroll
    for (int nb = 0; nb < 4; nb++) {
        int c = wn * 32 + nb * 8 + (lane & 3) * 2;
        bse[nb][0] = __ldg(bias + c);
        bse[nb][1] = __ldg(bias + c + 1);
    }
#pragma unroll
    for (int mi = 0; mi < 2; mi++) {
        int r0 = m0 + wm * 32 + mi * 16 + (lane >> 2);
        int r1 = r0 + 8;
        bool v0 = r0 < NN, v1 = r1 < NN;
#pragma unroll
        for (int nb = 0; nb < 4; nb++) {
            int c = wn * 32 + nb * 8 + (lane & 3) * 2;
            float o0 = acc[mi][nb][0] + bse[nb][0];
            float o1 = acc[mi][nb][1] + bse[nb][1];
            float o2 = acc[mi][nb][2] + bse[nb][0];
            float o3 = acc[mi][nb][3] + bse[nb][1];
            if (v0) {
                *(float2*)(outp + (size_t)r0 * HH + c) = make_float2(o0, o1);
                cs[nb][0] += o0; cs[nb][1] += o1;
                cq[nb][0] += o0 * o0; cq[nb][1] += o1 * o1;
            }
            if (v1) {
                *(float2*)(outp + (size_t)r1 * HH + c) = make_float2(o2, o3);
                cs[nb][0] += o2; cs[nb][1] += o3;
                cq[nb][0] += o2 * o2; cq[nb][1] += o3 * o3;
            }
        }
    }
#pragma unroll
    for (int nb = 0; nb < 4; nb++) {
#pragma unroll
        for (int j = 0; j < 2; j++) {
            float s = cs[nb][j], q = cq[nb][j];
#pragma unroll
            for (int off = 16; off >= 4; off >>= 1) {
                s += __shfl_down_sync(0xffffffffu, s, off);
                q += __shfl_down_sync(0xffffffffu, q, off);
            }
            if (lane < 4) {
                int c = wn * 32 + nb * 8 + lane * 2 + j;
                sS[wm * HH + c] = s;
                sQ[wm * HH + c] = q;
            }
        }
    }
    __syncthreads();
    if (tid < HH) {
        float s = sS[tid] + sS[HH + tid];
        float q = sQ[tid] + sQ[HH + tid];
        float* st = g_stats + ((MODE == 1) ? 0 : 2 * HH);
        atomicAdd(st + tid, s);
        atomicAdd(st + HH + tid, q);
    }
}

// pool: BN2 of last layer finalized per-block, scatter to g_pool
__global__ void __launch_bounds__(256)
k_pool(const int* __restrict__ batch,
       const float* __restrict__ bg, const float* __restrict__ bb) {
    __shared__ float s_sc[HH], s_sh[HH];
    const int tid = threadIdx.x;
    if (tid < HH) {
        float mu  = g_stats[2 * HH + tid] * (1.f / (float)NN);
        float msq = g_stats[3 * HH + tid] * (1.f / (float)NN);
        float rstd = rsqrtf(msq - mu * mu + 1e-5f);
        float s = __ldg(bg + tid) * rstd;
        s_sc[tid] = s;
        s_sh[tid] = __ldg(bb + tid) - s * mu;
    }
    __syncthreads();
    const int n = blockIdx.x * 8 + (tid >> 5);
    if (n >= NN) return;
    const int c = (tid & 31) << 2;
    float4 y = *(const float4*)(g_P + (size_t)n * HH + c);
    float4 o;
    o.x = fmaf(s_sc[c + 0], y.x, s_sh[c + 0]);
    o.y = fmaf(s_sc[c + 1], y.y, s_sh[c + 1]);
    o.z = fmaf(s_sc[c + 2], y.z, s_sh[c + 2]);
    o.w = fmaf(s_sc[c + 3], y.w, s_sh[c + 3]);
    red_add_v4(g_pool + (size_t)__ldg(batch + n) * HH + c, o);
}

__global__ void k_final(const float* __restrict__ cw1, const float* __restrict__ cb1,
                        const float* __restrict__ cw2, const float* __restrict__ cb2,
                        float* __restrict__ out) {
    __shared__ float p[HH];
    __shared__ float rb[4];
    int j = threadIdx.x;
    p[j] = g_pool[(size_t)blockIdx.x * HH + j];
    __syncthreads();
    float acc = __ldg(cb1 + j);
#pragma unroll 8
    for (int i = 0; i < HH; i++)
        acc = fmaf(p[i], __ldg(cw1 + i * HH + j), acc);
    float v = fmaxf(acc, 0.f) * __ldg(cw2 + j);
#pragma unroll
    for (int off = 16; off > 0; off >>= 1)
        v += __shfl_down_sync(0xffffffffu, v, off);
    if ((j & 31) == 0) rb[j >> 5] = v;
    __syncthreads();
    if (j == 0) out[blockIdx.x] = rb[0] + rb[1] + rb[2] + rb[3] + __ldg(cb2);
}

extern "C" void kernel_launch(void* const* d_in, const int* in_sizes, int n_in,
                              void* d_out, int out_size) {
    const int*   x     = (const int*)d_in[0];
    const int*   ei    = (const int*)d_in[1];
    const int*   ea    = (const int*)d_in[2];
    const int*   batch = (const int*)d_in[3];
    const float* aemb  = (const float*)d_in[4];
    const float* bemb  = (const float*)d_in[5];
    const float* eps   = (const float*)d_in[6];
    const float* w1    = (const float*)d_in[7];
    const float* b1    = (const float*)d_in[8];
    const float* bn1g  = (const float*)d_in[9];
    const float* bn1b  = (const float*)d_in[10];
    const float* w2    = (const float*)d_in[11];
    const float* b2    = (const float*)d_in[12];
    const float* bng   = (const float*)d_in[13];
    const float* bnb   = (const float*)d_in[14];
    const float* cw1   = (const float*)d_in[15];
    const float* cb1   = (const float*)d_in[16];
    const float* cw2   = (const float*)d_in[17];
    const float* cb2   = (const float*)d_in[18];
    float* out = (float*)d_out;
    const int* row = ei;
    const int* col = ei + EE;

    cudaFuncSetAttribute(k_mma<1>, cudaFuncAttributeMaxDynamicSharedMemorySize, GEMM_SMEM);
    cudaFuncSetAttribute(k_mma<2>, cudaFuncAttributeMaxDynamicSharedMemorySize, GEMM_SMEM);

    const int NT = 256;
    const int gridE  = (EE + NT - 1) / NT;
    const int gridGEMM = (NN + 63) / 64;          // 4688
    const int gridNode = (NN + 7) / 8;            // 37500

    k_init<<<2048, NT>>>();
    k_prepw<<<dim3(16, 10), 256>>>(w1, w2);
    k_prepbond<<<dim3(216, 5), HH>>>(bemb);
    k_cnt<<<gridE, NT>>>(row, col);
    k_scan<<<2, 1024>>>();
    k_fill<<<gridE, NT>>>(row, col, ea);
    for (int l = 0; l < 5; l++) {
        if (l == 0)
            k_node<1><<<gridNode, NT>>>(0, nullptr, nullptr, x, aemb);
        else
            k_node<0><<<gridNode, NT>>>(l, bng + (l - 1) * HH, bnb + (l - 1) * HH,
                                        nullptr, nullptr);
        k_mma<1><<<gridGEMM, NT, GEMM_SMEM>>>(2 * l, b1 + l * HH, eps + l, nullptr, nullptr);
        k_mma<2><<<gridGEMM, NT, GEMM_SMEM>>>(2 * l + 1, b2 + l * HH, nullptr,
                                              bn1g + l * HH, bn1b + l * HH);
    }
    k_pool<<<gridNode, NT>>>(batch, bng + 4 * HH, bnb + 4 * HH);
    k_final<<<GG, HH>>>(cw1, cb1, cw2, cb2, out);
}